// round 13
// baseline (speedup 1.0000x reference)
#include <cuda_runtime.h>
#include <math.h>

// ---------------------------------------------------------------------------
// GCN 2-layer forward:  out = log_softmax( A' relu(A' (x W1) + b1) W2 + b2 )
// A' = D^-1/2 (A + I) D^-1/2.
//
// R12 = R11 resubmitted verbatim (R11 bench was an infra failure, never ran).
//   0 k_hist        degree histogram
//   1 k_scan_fused  rowoff/cursor/dinv, restores g_cnt=0
//   2 k_scatter     CSR fill
//   3 k_gemm<128,0> hs1 = dinv_i * (x W1)            <- ncu slot (R9-style)
//   4 k_agg_ps<1>   h2p = dinv*relu(dinv*(sum hs1_j + hs1_i) + b1)
//   5 k_agg_ps<0>   ah  = dinv*(sum h2p_j + h2p_i)
//   6 k_gemm<64,1>  z   = ah W2 + b2
//   7 k_softmax     out = log_softmax(z)
// ---------------------------------------------------------------------------

#define NMAX 100000
#define EMAX 1600000

__device__ int g_cnt[NMAX];          // zero at module load; self-restored each call
__device__ int g_rowoff[NMAX + 1];
__device__ int g_cursor[NMAX];
__device__ float g_dinv[NMAX];
__device__ int g_csr[EMAX];
__device__ __align__(16) float g_hs1[(size_t)NMAX * 128];  // dinv_i * (x W1)
__device__ __align__(16) float g_h2p[(size_t)NMAX * 128];  // dinv_i * relu(...)
__device__ __align__(16) float g_ah[(size_t)NMAX * 128];   // dinv_i * sum h2p
__device__ __align__(16) float g_z[(size_t)NMAX * 64];     // ah W2 + b2

// ---------------------------------------------------------------------------
__global__ void k_hist(const int* __restrict__ dst, int e) {
    int i = blockIdx.x * blockDim.x + threadIdx.x;
    if (i < e) atomicAdd(&g_cnt[dst[i]], 1);
}

// Single-block fused: exclusive scan of g_cnt -> g_rowoff & g_cursor,
// dinv = rsqrt(cnt+1), and zero g_cnt (restore invariant for next call).
__global__ void k_scan_fused(int n, int e) {
    __shared__ int warp_sums[32];
    __shared__ int s_base;
    const int t = threadIdx.x;
    const int lane = t & 31, wid = t >> 5;
    if (t == 0) s_base = 0;
    __syncthreads();

    for (int start = 0; start < n; start += 1024) {
        int i = start + t;
        int v = (i < n) ? g_cnt[i] : 0;

        int sc = v;
#pragma unroll
        for (int o = 1; o < 32; o <<= 1) {
            int u = __shfl_up_sync(0xffffffffu, sc, o);
            if (lane >= o) sc += u;
        }
        if (lane == 31) warp_sums[wid] = sc;
        __syncthreads();
        if (wid == 0) {
            int ws = warp_sums[lane];
#pragma unroll
            for (int o = 1; o < 32; o <<= 1) {
                int u = __shfl_up_sync(0xffffffffu, ws, o);
                if (lane >= o) ws += u;
            }
            warp_sums[lane] = ws;
        }
        __syncthreads();

        int excl = sc - v + (wid ? warp_sums[wid - 1] : 0) + s_base;
        if (i < n) {
            g_rowoff[i] = excl;
            g_cursor[i] = excl;
            g_dinv[i] = rsqrtf((float)(v + 1));  // +1 self loop
            g_cnt[i] = 0;
        }
        __syncthreads();
        if (t == 0) s_base += warp_sums[31];
        __syncthreads();
    }
    if (t == 0) g_rowoff[n] = e;
}

__global__ void k_scatter(const int* __restrict__ src, const int* __restrict__ dst, int e) {
    int i = blockIdx.x * blockDim.x + threadIdx.x;
    if (i < e) {
        int d = dst[i];
        int p = atomicAdd(&g_cursor[d], 1);
        g_csr[p] = src[i];
    }
}

// ---------------------------------------------------------------------------
// GEMM (R9-style, known 395us @ NC=128): acc[i][c] = sum_k X[i][k]*W[k][c]
// Block: 64 rows x NC cols, 256 threads, thread = 4 rows x NC/16 cols.
// EPI 0: out = dinv[i]*acc          (prescale rows for downstream agg)
// EPI 1: out = acc + bias[c]        (layer-2 logits)
// ---------------------------------------------------------------------------
#define XS_STRIDE 129

template <int NC, int EPI>
__global__ void k_gemm(const float* __restrict__ X, const float* __restrict__ W,
                       const float* __restrict__ bias, float* __restrict__ out, int n) {
    extern __shared__ float sm[];
    float* Ws = sm;                 // 128 * NC
    float* Xs = sm + 128 * NC;      // 64 * XS_STRIDE
    const int tid = threadIdx.x;
    const int row0 = blockIdx.x * 64;

    for (int i = tid; i < 128 * NC; i += 256) Ws[i] = W[i];
    for (int i = tid; i < 64 * 128; i += 256) {
        int r = i >> 7, c = i & 127;
        int gr = row0 + r;
        Xs[r * XS_STRIDE + c] = (gr < n) ? X[(size_t)gr * 128 + c] : 0.f;
    }
    __syncthreads();

    const int tr = tid >> 4;
    const int tc = tid & 15;
    constexpr int TN = NC / 16;
    float acc[4][TN];
#pragma unroll
    for (int r = 0; r < 4; r++)
#pragma unroll
        for (int j = 0; j < TN; j++) acc[r][j] = 0.f;

#pragma unroll 2
    for (int k = 0; k < 128; k++) {
        float xr[4];
#pragma unroll
        for (int r = 0; r < 4; r++) xr[r] = Xs[(tr * 4 + r) * XS_STRIDE + k];
#pragma unroll
        for (int j = 0; j < TN; j++) {
            float w = Ws[k * NC + tc + 16 * j];
#pragma unroll
            for (int r = 0; r < 4; r++) acc[r][j] = fmaf(xr[r], w, acc[r][j]);
        }
    }

#pragma unroll
    for (int r = 0; r < 4; r++) {
        int gr = row0 + tr * 4 + r;
        if (gr < n) {
            if (EPI == 0) {
                float dv = g_dinv[gr];
#pragma unroll
                for (int j = 0; j < TN; j++)
                    out[(size_t)gr * NC + tc + 16 * j] = dv * acc[r][j];
            } else {
#pragma unroll
                for (int j = 0; j < TN; j++)
                    out[(size_t)gr * NC + tc + 16 * j] = acc[r][j] + bias[tc + 16 * j];
            }
        }
    }
}

// ---------------------------------------------------------------------------
// Prescaled 128-dim gather aggregation (the one proven-fast pattern).
// Block = 128 threads = one node, thread t = column t. Rows of `hp` are
// already scaled by their own dinv, so per-neighbor work is a pure add.
//   acc = hp[i,t] + sum_j hp[j,t]
// EPI 1: out = dinv_i * relu( dinv_i*acc + bias[t] )   (h2p, prescaled out)
// EPI 0: out = dinv_i * acc                            (ah)
// ---------------------------------------------------------------------------
#define AGG_CH 128

template <int EPI>
__global__ void k_agg_ps(const float* __restrict__ hp, const float* __restrict__ bias,
                         float* __restrict__ out, int n) {
    __shared__ int s_idx[AGG_CH];
    const int node = blockIdx.x;
    const int t = threadIdx.x;
    const float* __restrict__ hc = hp + t;

    float acc = hc[(size_t)node * 128];  // self loop (row already dinv-scaled)

    const int p = g_rowoff[node];
    const int end = g_rowoff[node + 1];

    for (int base = p; base < end; base += AGG_CH) {
        const int nv = min(AGG_CH, end - base);
        __syncthreads();
        if (t < nv) s_idx[t] = g_csr[base + t];
        __syncthreads();
        int m = 0;
        for (; m + 8 <= nv; m += 8) {
            int j0 = s_idx[m + 0], j1 = s_idx[m + 1], j2 = s_idx[m + 2], j3 = s_idx[m + 3];
            int j4 = s_idx[m + 4], j5 = s_idx[m + 5], j6 = s_idx[m + 6], j7 = s_idx[m + 7];
            float v0 = hc[(size_t)j0 * 128];
            float v1 = hc[(size_t)j1 * 128];
            float v2 = hc[(size_t)j2 * 128];
            float v3 = hc[(size_t)j3 * 128];
            float v4 = hc[(size_t)j4 * 128];
            float v5 = hc[(size_t)j5 * 128];
            float v6 = hc[(size_t)j6 * 128];
            float v7 = hc[(size_t)j7 * 128];
            acc += ((v0 + v1) + (v2 + v3)) + ((v4 + v5) + (v6 + v7));
        }
        for (; m < nv; m++)
            acc += hc[(size_t)s_idx[m] * 128];
    }

    const float di = g_dinv[node];
    if (EPI == 1) {
        float r = fmaxf(fmaf(di, acc, bias[t]), 0.f);
        out[(size_t)node * 128 + t] = di * r;
    } else {
        out[(size_t)node * 128 + t] = di * acc;
    }
}

// ---------------------------------------------------------------------------
// Row-wise log_softmax over [n,64]. Block = 64 threads = one node.
// ---------------------------------------------------------------------------
__global__ void k_softmax(const float* __restrict__ z, float* __restrict__ out, int n) {
    __shared__ float s_m[2], s_s[2];
    const int node = blockIdx.x;
    const int t = threadIdx.x;
    const int lane = t & 31, wid = t >> 5;

    float o = z[(size_t)node * 64 + t];

    float mx = o;
#pragma unroll
    for (int off = 16; off; off >>= 1) mx = fmaxf(mx, __shfl_xor_sync(0xffffffffu, mx, off));
    if (lane == 0) s_m[wid] = mx;
    __syncthreads();
    mx = fmaxf(s_m[0], s_m[1]);

    float ss = expf(o - mx);
#pragma unroll
    for (int off = 16; off; off >>= 1) ss += __shfl_xor_sync(0xffffffffu, ss, off);
    if (lane == 0) s_s[wid] = ss;
    __syncthreads();
    float lse = mx + logf(s_s[0] + s_s[1]);

    out[(size_t)node * 64 + t] = o - lse;
}

// ---------------------------------------------------------------------------
extern "C" void kernel_launch(void* const* d_in, const int* in_sizes, int n_in,
                              void* d_out, int out_size) {
    const float* x  = (const float*)d_in[0];
    const int*   ei = (const int*)d_in[1];
    const float* W1 = (const float*)d_in[2];
    const float* b1 = (const float*)d_in[3];
    const float* W2 = (const float*)d_in[4];
    const float* b2 = (const float*)d_in[5];
    float* out = (float*)d_out;

    const int n = in_sizes[0] / 128;
    const int e = in_sizes[1] / 2;
    const int* src = ei;
    const int* dst = ei + e;

    const int TB = 256;
    const int gE = (e + TB - 1) / TB;
    const int gG = (n + 63) / 64;

    const int SM1 = (128 * 128 + 64 * XS_STRIDE) * 4;  // 98560 B
    const int SM2 = (128 * 64 + 64 * XS_STRIDE) * 4;   // 65792 B
    cudaFuncSetAttribute((const void*)k_gemm<128, 0>, cudaFuncAttributeMaxDynamicSharedMemorySize, SM1);
    cudaFuncSetAttribute((const void*)k_gemm<64, 1>,  cudaFuncAttributeMaxDynamicSharedMemorySize, SM2);

    k_hist<<<gE, TB>>>(dst, e);                                   // 0
    k_scan_fused<<<1, 1024>>>(n, e);                              // 1
    k_scatter<<<gE, TB>>>(src, dst, e);                           // 2
    k_gemm<128, 0><<<gG, 256, SM1>>>(x, W1, nullptr, g_hs1, n);   // 3  <- ncu slot
    k_agg_ps<1><<<n, 128>>>(g_hs1, b1, g_h2p, n);                 // 4
    k_agg_ps<0><<<n, 128>>>(g_h2p, nullptr, g_ah, n);             // 5
    k_gemm<64, 1><<<gG, 256, SM2>>>(g_ah, W2, b2, g_z, n);        // 6
    k_softmax<<<n, 64>>>(g_z, out, n);                            // 7
}

// round 14
// speedup vs baseline: 6.7520x; 6.7520x over previous
#include <cuda_runtime.h>
#include <math.h>

// ---------------------------------------------------------------------------
// GCN 2-layer forward:  out = log_softmax( A' relu(A' (x W1) + b1) W2 + b2 )
// A' = D^-1/2 (A + I) D^-1/2.
//
// R13 key insight: random gathers from __device__ globals are ~10x slower
// than from harness-cudaMalloc'ed buffers (small-page TLB thrash). So every
// gather source is a harness buffer:
//   layer 1 aggregate-first: gather from x            (input buffer)
//   layer 2 transform-first: zs staged in d_out, gather from d_out
//
//   0 k_hist        degree histogram
//   1 k_scan_fused  rowoff/cursor/dinv, restores g_cnt=0
//   2 k_scatter     CSR fill
//   3 k_agg1        ax = dinv*(dinv*x_i + sum dinv_j x_j)   <- ncu slot (=358us ref)
//   4 k_gemm<128,1> h2 = relu(ax W1 + b1)
//   5 k_gemm<64,0>  d_out := zs = dinv * (h2 W2)
//   6 k_agg2sm      z2 = log_softmax(dinv*(sum zs_j + zs_i) + b2)  [gathers d_out]
//   7 k_copy        d_out := z2
// ---------------------------------------------------------------------------

#define NMAX 100000
#define EMAX 1600000

__device__ int g_cnt[NMAX];          // zero at module load; self-restored each call
__device__ int g_rowoff[NMAX + 1];
__device__ int g_cursor[NMAX];
__device__ float g_dinv[NMAX];
__device__ int g_csr[EMAX];
__device__ __align__(16) float g_ax[(size_t)NMAX * 128];   // A'x (streaming use only)
__device__ __align__(16) float g_h2[(size_t)NMAX * 128];   // relu(ax W1 + b1)
__device__ __align__(16) float g_z2[(size_t)NMAX * 64];    // final log-softmax rows

// ---------------------------------------------------------------------------
__global__ void k_hist(const int* __restrict__ dst, int e) {
    int i = blockIdx.x * blockDim.x + threadIdx.x;
    if (i < e) atomicAdd(&g_cnt[dst[i]], 1);
}

// Single-block fused: exclusive scan of g_cnt -> g_rowoff & g_cursor,
// dinv = rsqrt(cnt+1), and zero g_cnt (restore invariant for next call).
__global__ void k_scan_fused(int n, int e) {
    __shared__ int warp_sums[32];
    __shared__ int s_base;
    const int t = threadIdx.x;
    const int lane = t & 31, wid = t >> 5;
    if (t == 0) s_base = 0;
    __syncthreads();

    for (int start = 0; start < n; start += 1024) {
        int i = start + t;
        int v = (i < n) ? g_cnt[i] : 0;

        int sc = v;
#pragma unroll
        for (int o = 1; o < 32; o <<= 1) {
            int u = __shfl_up_sync(0xffffffffu, sc, o);
            if (lane >= o) sc += u;
        }
        if (lane == 31) warp_sums[wid] = sc;
        __syncthreads();
        if (wid == 0) {
            int ws = warp_sums[lane];
#pragma unroll
            for (int o = 1; o < 32; o <<= 1) {
                int u = __shfl_up_sync(0xffffffffu, ws, o);
                if (lane >= o) ws += u;
            }
            warp_sums[lane] = ws;
        }
        __syncthreads();

        int excl = sc - v + (wid ? warp_sums[wid - 1] : 0) + s_base;
        if (i < n) {
            g_rowoff[i] = excl;
            g_cursor[i] = excl;
            g_dinv[i] = rsqrtf((float)(v + 1));  // +1 self loop
            g_cnt[i] = 0;
        }
        __syncthreads();
        if (t == 0) s_base += warp_sums[31];
        __syncthreads();
    }
    if (t == 0) g_rowoff[n] = e;
}

__global__ void k_scatter(const int* __restrict__ src, const int* __restrict__ dst, int e) {
    int i = blockIdx.x * blockDim.x + threadIdx.x;
    if (i < e) {
        int d = dst[i];
        int p = atomicAdd(&g_cursor[d], 1);
        g_csr[p] = src[i];
    }
}

// ---------------------------------------------------------------------------
// Layer-1 aggregation on raw input x (aggregate-first). BYTE-IDENTICAL to the
// R10-measured 358us kernel. Block = 128 threads = one node, thread = column.
//   ax[i,t] = dinv_i * ( dinv_i * x[i,t] + sum_j dinv_j * x[j,t] )
// ---------------------------------------------------------------------------
#define AGG_CH 128

__global__ void k_agg1(const float* __restrict__ x, float* __restrict__ out, int n) {
    __shared__ int s_idx[AGG_CH];
    __shared__ float s_d[AGG_CH];
    const int node = blockIdx.x;
    const int t = threadIdx.x;
    const float* __restrict__ xc = x + t;

    const float di = g_dinv[node];
    float acc = di * xc[(size_t)node * 128];  // self loop

    const int p = g_rowoff[node];
    const int end = g_rowoff[node + 1];

    for (int base = p; base < end; base += AGG_CH) {
        const int nv = min(AGG_CH, end - base);
        __syncthreads();
        if (t < nv) {
            int j = g_csr[base + t];
            s_idx[t] = j;
            s_d[t] = g_dinv[j];
        }
        __syncthreads();
        int m = 0;
        for (; m + 8 <= nv; m += 8) {
            int j0 = s_idx[m + 0], j1 = s_idx[m + 1], j2 = s_idx[m + 2], j3 = s_idx[m + 3];
            int j4 = s_idx[m + 4], j5 = s_idx[m + 5], j6 = s_idx[m + 6], j7 = s_idx[m + 7];
            float d0 = s_d[m + 0], d1 = s_d[m + 1], d2 = s_d[m + 2], d3 = s_d[m + 3];
            float d4 = s_d[m + 4], d5 = s_d[m + 5], d6 = s_d[m + 6], d7 = s_d[m + 7];
            float v0 = xc[(size_t)j0 * 128];
            float v1 = xc[(size_t)j1 * 128];
            float v2 = xc[(size_t)j2 * 128];
            float v3 = xc[(size_t)j3 * 128];
            float v4 = xc[(size_t)j4 * 128];
            float v5 = xc[(size_t)j5 * 128];
            float v6 = xc[(size_t)j6 * 128];
            float v7 = xc[(size_t)j7 * 128];
            acc = fmaf(d0, v0, acc); acc = fmaf(d1, v1, acc);
            acc = fmaf(d2, v2, acc); acc = fmaf(d3, v3, acc);
            acc = fmaf(d4, v4, acc); acc = fmaf(d5, v5, acc);
            acc = fmaf(d6, v6, acc); acc = fmaf(d7, v7, acc);
        }
        for (; m < nv; m++)
            acc = fmaf(s_d[m], xc[(size_t)s_idx[m] * 128], acc);
    }

    out[(size_t)node * 128 + t] = di * acc;
}

// ---------------------------------------------------------------------------
// GEMM (R9-style): acc[i][c] = sum_k X[i][k]*W[k][c]   (K = 128 fixed)
// Block: 64 rows x NC cols, 256 threads, thread = 4 rows x NC/16 cols.
// EPI 0: out = dinv[i]*acc           (zs rows, prescaled for layer-2 agg)
// EPI 1: out = relu(acc + bias[c])   (h2)
// ---------------------------------------------------------------------------
#define XS_STRIDE 129

template <int NC, int EPI>
__global__ void k_gemm(const float* __restrict__ X, const float* __restrict__ W,
                       const float* __restrict__ bias, float* __restrict__ out, int n) {
    extern __shared__ float sm[];
    float* Ws = sm;                 // 128 * NC
    float* Xs = sm + 128 * NC;      // 64 * XS_STRIDE
    const int tid = threadIdx.x;
    const int row0 = blockIdx.x * 64;

    for (int i = tid; i < 128 * NC; i += 256) Ws[i] = W[i];
    for (int i = tid; i < 64 * 128; i += 256) {
        int r = i >> 7, c = i & 127;
        int gr = row0 + r;
        Xs[r * XS_STRIDE + c] = (gr < n) ? X[(size_t)gr * 128 + c] : 0.f;
    }
    __syncthreads();

    const int tr = tid >> 4;
    const int tc = tid & 15;
    constexpr int TN = NC / 16;
    float acc[4][TN];
#pragma unroll
    for (int r = 0; r < 4; r++)
#pragma unroll
        for (int j = 0; j < TN; j++) acc[r][j] = 0.f;

#pragma unroll 2
    for (int k = 0; k < 128; k++) {
        float xr[4];
#pragma unroll
        for (int r = 0; r < 4; r++) xr[r] = Xs[(tr * 4 + r) * XS_STRIDE + k];
#pragma unroll
        for (int j = 0; j < TN; j++) {
            float w = Ws[k * NC + tc + 16 * j];
#pragma unroll
            for (int r = 0; r < 4; r++) acc[r][j] = fmaf(xr[r], w, acc[r][j]);
        }
    }

#pragma unroll
    for (int r = 0; r < 4; r++) {
        int gr = row0 + tr * 4 + r;
        if (gr < n) {
            if (EPI == 0) {
                float dv = g_dinv[gr];
#pragma unroll
                for (int j = 0; j < TN; j++)
                    out[(size_t)gr * NC + tc + 16 * j] = dv * acc[r][j];
            } else {
#pragma unroll
                for (int j = 0; j < TN; j++)
                    out[(size_t)gr * NC + tc + 16 * j] =
                        fmaxf(acc[r][j] + bias[tc + 16 * j], 0.f);
            }
        }
    }
}

// ---------------------------------------------------------------------------
// Layer-2 aggregation + bias + log_softmax. Block = 64 threads = one node.
// Gathers zs rows FROM d_out (harness buffer -> 2MB pages -> fast).
// zs rows are prescaled by dinv_j, so per-neighbor work is a pure add.
//   o = dinv_i*(zs_i + sum_j zs_j) + b2 ; out = o - logsumexp(o)
// Writes to g_z2 (streaming) — cannot write d_out in place while other
// blocks still gather from it.
// ---------------------------------------------------------------------------
__global__ void k_agg2sm(const float* __restrict__ zs, const float* __restrict__ bias,
                         float* __restrict__ outz, int n) {
    __shared__ int s_idx[64];
    __shared__ float s_m[2], s_s[2];
    const int node = blockIdx.x;
    const int t = threadIdx.x;        // 0..63 column
    const int lane = t & 31, wid = t >> 5;
    const float* __restrict__ zc = zs + t;

    float acc = zc[(size_t)node * 64];   // self loop
    const int p = g_rowoff[node];
    const int end = g_rowoff[node + 1];

    for (int base = p; base < end; base += 64) {
        const int nv = min(64, end - base);
        __syncthreads();
        if (t < nv) s_idx[t] = g_csr[base + t];
        __syncthreads();
        int m = 0;
        for (; m + 8 <= nv; m += 8) {
            int j0 = s_idx[m + 0], j1 = s_idx[m + 1], j2 = s_idx[m + 2], j3 = s_idx[m + 3];
            int j4 = s_idx[m + 4], j5 = s_idx[m + 5], j6 = s_idx[m + 6], j7 = s_idx[m + 7];
            float v0 = zc[(size_t)j0 * 64];
            float v1 = zc[(size_t)j1 * 64];
            float v2 = zc[(size_t)j2 * 64];
            float v3 = zc[(size_t)j3 * 64];
            float v4 = zc[(size_t)j4 * 64];
            float v5 = zc[(size_t)j5 * 64];
            float v6 = zc[(size_t)j6 * 64];
            float v7 = zc[(size_t)j7 * 64];
            acc += ((v0 + v1) + (v2 + v3)) + ((v4 + v5) + (v6 + v7));
        }
        for (; m < nv; m++)
            acc += zc[(size_t)s_idx[m] * 64];
    }

    float o = fmaf(g_dinv[node], acc, bias[t]);

    // log_softmax over the 64 values held by this block (2 warps)
    float mx = o;
#pragma unroll
    for (int off = 16; off; off >>= 1) mx = fmaxf(mx, __shfl_xor_sync(0xffffffffu, mx, off));
    if (lane == 0) s_m[wid] = mx;
    __syncthreads();
    mx = fmaxf(s_m[0], s_m[1]);

    float ss = expf(o - mx);
#pragma unroll
    for (int off = 16; off; off >>= 1) ss += __shfl_xor_sync(0xffffffffu, ss, off);
    if (lane == 0) s_s[wid] = ss;
    __syncthreads();
    float lse = mx + logf(s_s[0] + s_s[1]);

    outz[(size_t)node * 64 + t] = o - lse;
}

// float4 copy: d_out := g_z2
__global__ void k_copy(float4* __restrict__ dst, const float4* __restrict__ src, int n4) {
    int i = blockIdx.x * blockDim.x + threadIdx.x;
    if (i < n4) dst[i] = src[i];
}

// ---------------------------------------------------------------------------
extern "C" void kernel_launch(void* const* d_in, const int* in_sizes, int n_in,
                              void* d_out, int out_size) {
    const float* x  = (const float*)d_in[0];
    const int*   ei = (const int*)d_in[1];
    const float* W1 = (const float*)d_in[2];
    const float* b1 = (const float*)d_in[3];
    const float* W2 = (const float*)d_in[4];
    const float* b2 = (const float*)d_in[5];
    float* out = (float*)d_out;

    const int n = in_sizes[0] / 128;
    const int e = in_sizes[1] / 2;
    const int* src = ei;
    const int* dst = ei + e;

    const int TB = 256;
    const int gE = (e + TB - 1) / TB;
    const int gG = (n + 63) / 64;
    const int n4 = n * 16;                      // n*64 floats / 4
    const int gC = (n4 + TB - 1) / TB;

    const int SM1 = (128 * 128 + 64 * XS_STRIDE) * 4;  // 98560 B
    const int SM2 = (128 * 64 + 64 * XS_STRIDE) * 4;   // 65792 B
    cudaFuncSetAttribute((const void*)k_gemm<128, 1>, cudaFuncAttributeMaxDynamicSharedMemorySize, SM1);
    cudaFuncSetAttribute((const void*)k_gemm<64, 0>,  cudaFuncAttributeMaxDynamicSharedMemorySize, SM2);

    k_hist<<<gE, TB>>>(dst, e);                                   // 0
    k_scan_fused<<<1, 1024>>>(n, e);                              // 1
    k_scatter<<<gE, TB>>>(src, dst, e);                           // 2
    k_agg1<<<n, 128>>>(x, g_ax, n);                               // 3  <- ncu slot (358us ref)
    k_gemm<128, 1><<<gG, 256, SM1>>>(g_ax, W1, b1, g_h2, n);      // 4
    k_gemm<64, 0><<<gG, 256, SM2>>>(g_h2, W2, nullptr, out, n);   // 5  zs -> d_out
    k_agg2sm<<<n, 64>>>(out, b2, g_z2, n);                        // 6  gathers d_out
    k_copy<<<gC, TB>>>((float4*)out, (const float4*)g_z2, n4);    // 7
}